// round 13
// baseline (speedup 1.0000x reference)
#include <cuda_runtime.h>

typedef unsigned long long U64;

#define NUM_HEADS 8
#define HDIM 512
#define NGRAPH 256

// ---------------- device scratch (no allocations allowed) ----------------
__device__ float g_qk[NUM_HEADS * HDIM];
__device__ float g_y[NGRAPH][NUM_HEADS][HDIM];
__device__ float g_denom[NGRAPH][NUM_HEADS];
__device__ float g_att[NGRAPH][HDIM];

// ---------------- f32x2 helpers ----------------
__device__ __forceinline__ U64 fma2(U64 a, U64 b, U64 c) {
    U64 d;
    asm("fma.rn.f32x2 %0, %1, %2, %3;" : "=l"(d) : "l"(a), "l"(b), "l"(c));
    return d;
}
__device__ __forceinline__ U64 add2(U64 a, U64 b) {
    U64 d;
    asm("add.rn.f32x2 %0, %1, %2;" : "=l"(d) : "l"(a), "l"(b));
    return d;
}
__device__ __forceinline__ U64 dup2(float x) {
    U64 d; unsigned xi = __float_as_uint(x);
    asm("mov.b64 %0, {%1, %1};" : "=l"(d) : "r"(xi));
    return d;
}
__device__ __forceinline__ U64 pack2(float a, float b) {
    U64 d;
    asm("mov.b64 %0, {%1, %2};" : "=l"(d)
        : "r"(__float_as_uint(a)), "r"(__float_as_uint(b)));
    return d;
}
__device__ __forceinline__ float lo2(U64 v) { return __uint_as_float((unsigned)(v & 0xffffffffu)); }
__device__ __forceinline__ float hi2(U64 v) { return __uint_as_float((unsigned)(v >> 32)); }

__device__ __forceinline__ void cpa16(void* dst, const void* src) {
    unsigned d = (unsigned)__cvta_generic_to_shared(dst);
    asm volatile("cp.async.cg.shared.global [%0], [%1], 16;\n" :: "r"(d), "l"(src));
}
#define CP_COMMIT() asm volatile("cp.async.commit_group;\n" ::: "memory")
#define CP_WAIT0()  asm volatile("cp.async.wait_group 0;\n" ::: "memory")

// ---------------- zero kernels (atomic accumulators) ----------------
__global__ void zero_y_kernel() {
    int i = (blockIdx.x * 256 + threadIdx.x) * 4;   // 1024 CTAs -> 1,048,576 floats
    *(float4*)&(((float*)g_y)[i]) = make_float4(0.f, 0.f, 0.f, 0.f);
}
__global__ void zero_d_kernel() {
    int i = blockIdx.x * 256 + threadIdx.x;          // 8 CTAs -> 2048 floats
    ((float*)g_denom)[i] = 0.f;
}

// ---------------- qk fold (64 CTAs, smem-staged coalesced) ----------------
__global__ __launch_bounds__(256) void qk_kernel(const float* __restrict__ q,
                                                 const float* __restrict__ kw) {
    __shared__ float tile[64 * 65];
    __shared__ float qs[64];
    __shared__ float part[4][64];
    const int h = blockIdx.x >> 3, jb = blockIdx.x & 7;
    const int t = threadIdx.x;
    if (t < 64) qs[t] = q[h * 64 + t];
    for (int k = t; k < 1024; k += 256) {
        int r = k >> 4, cc = k & 15;
        float4 v = *(const float4*)&kw[(size_t)(h * 64 + r) * HDIM + jb * 64 + cc * 4];
        float* dst = &tile[r * 65 + cc * 4];
        dst[0] = v.x; dst[1] = v.y; dst[2] = v.z; dst[3] = v.w;
    }
    __syncthreads();
    const int c = t & 63, ds = t >> 6;
    float s = 0.f;
#pragma unroll
    for (int d = 0; d < 16; d++) s += qs[ds * 16 + d] * tile[(ds * 16 + d) * 65 + c];
    part[ds][c] = s;
    __syncthreads();
    if (t < 64)
        g_qk[h * HDIM + jb * 64 + t] =
            (part[0][t] + part[1][t] + part[2][t] + part[3][t]) * 0.125f;
}

// ---------------- main: register-resident, 2-node interleaved (PROC2) ----------------
// Warp w: heads {2(w&3), 2(w&3)+1}, node-lane nl = w>>2 -> contiguous node range.
// Lane owns 16 dims (4 float4s at lane*4 + p*128).
// PROC2: dot(B0=rn) + dot(B1=rn+1) back-to-back (8 indep fma2 chains) ->
//   refill B0<-rn+2, B1<-rn+3 -> 4 interleaved shfl butterflies -> 2x exp ->
//   Phase B for both nodes (x re-read from L1; lines resident).
__global__ __launch_bounds__(256, 2)
void main_kernel(const float* __restrict__ x, const int* __restrict__ batch,
                 int N, int CHv) {
    const int t = threadIdx.x;
    const int lane = t & 31;
    const int w = t >> 5;
    const int h0 = (w & 3) * 2;
    const int nl = w >> 2;

    U64 q0[8], q1[8];
#pragma unroll
    for (int p = 0; p < 4; p++) {
        int d = p * 128 + lane * 4;
        ulonglong2 a = *(const ulonglong2*)&g_qk[h0 * HDIM + d];
        ulonglong2 b = *(const ulonglong2*)&g_qk[(h0 + 1) * HDIM + d];
        q0[2 * p] = a.x; q0[2 * p + 1] = a.y;
        q1[2 * p] = b.x; q1[2 * p + 1] = b.y;
    }

    U64 Y0[8], Y1[8];
#pragma unroll
    for (int p = 0; p < 8; p++) { Y0[p] = 0ull; Y1[p] = 0ull; }
    U64 dp = 0ull;
    int cur_g = -1;

    const int half = CHv >> 1;
    const int nbeg = blockIdx.x * CHv + nl * half;
    const int nlim = min(nbeg + half, N);
    const int count = nlim - nbeg;

    const float* pcur = x + (size_t)nbeg * HDIM + lane * 4;
    const int* bptr = batch + nbeg;
    int rn = 0;

    U64 B0[8], B1[8];

#define FLUSH() do {                                                          \
        _Pragma("unroll")                                                     \
        for (int p = 0; p < 4; p++) {                                         \
            int d = p * 128 + lane * 4;                                       \
            atomicAdd(&g_y[cur_g][h0][d],         lo2(Y0[2 * p]));            \
            atomicAdd(&g_y[cur_g][h0][d + 1],     hi2(Y0[2 * p]));            \
            atomicAdd(&g_y[cur_g][h0][d + 2],     lo2(Y0[2 * p + 1]));        \
            atomicAdd(&g_y[cur_g][h0][d + 3],     hi2(Y0[2 * p + 1]));        \
            atomicAdd(&g_y[cur_g][h0 + 1][d],     lo2(Y1[2 * p]));            \
            atomicAdd(&g_y[cur_g][h0 + 1][d + 1], hi2(Y1[2 * p]));            \
            atomicAdd(&g_y[cur_g][h0 + 1][d + 2], lo2(Y1[2 * p + 1]));        \
            atomicAdd(&g_y[cur_g][h0 + 1][d + 3], hi2(Y1[2 * p + 1]));        \
            Y0[2 * p] = 0ull; Y0[2 * p + 1] = 0ull;                           \
            Y1[2 * p] = 0ull; Y1[2 * p + 1] = 0ull;                           \
        }                                                                     \
        if (lane == 0) {                                                      \
            atomicAdd(&g_denom[cur_g][h0],     lo2(dp));                      \
            atomicAdd(&g_denom[cur_g][h0 + 1], hi2(dp));                      \
        }                                                                     \
        dp = 0ull;                                                            \
    } while (0)

#define LOADB(SL, PTR) do {                                                   \
        _Pragma("unroll")                                                     \
        for (int p = 0; p < 4; p++) {                                         \
            ulonglong2 v = *(const ulonglong2*)&(PTR)[p * 128];               \
            B##SL[2 * p] = v.x; B##SL[2 * p + 1] = v.y;                       \
        }                                                                     \
    } while (0)

#define PHASEB(PTR, WD0, WD1) do {                                            \
        _Pragma("unroll")                                                     \
        for (int p = 0; p < 4; p++) {                                         \
            ulonglong2 v = *(const ulonglong2*)&(PTR)[p * 128];               \
            Y0[2 * p]     = fma2(WD0, v.x, Y0[2 * p]);                        \
            Y0[2 * p + 1] = fma2(WD0, v.y, Y0[2 * p + 1]);                    \
            Y1[2 * p]     = fma2(WD1, v.x, Y1[2 * p]);                        \
            Y1[2 * p + 1] = fma2(WD1, v.y, Y1[2 * p + 1]);                    \
        }                                                                     \
    } while (0)

    if (count > 0) LOADB(0, pcur);
    if (count > 1) LOADB(1, pcur + HDIM);

    while (rn + 1 < count) {
        // ---- two dots, 8 independent fma2 chains ----
        U64 a0 = 0ull, a1 = 0ull, b0 = 0ull, b1 = 0ull;
        U64 c0 = 0ull, c1 = 0ull, d0 = 0ull, d1 = 0ull;
#pragma unroll
        for (int p = 0; p < 4; p++) {
            a0 = fma2(B0[2 * p],     q0[2 * p],     a0);
            a1 = fma2(B0[2 * p + 1], q0[2 * p + 1], a1);
            b0 = fma2(B0[2 * p],     q1[2 * p],     b0);
            b1 = fma2(B0[2 * p + 1], q1[2 * p + 1], b1);
            c0 = fma2(B1[2 * p],     q0[2 * p],     c0);
            c1 = fma2(B1[2 * p + 1], q0[2 * p + 1], c1);
            d0 = fma2(B1[2 * p],     q1[2 * p],     d0);
            d1 = fma2(B1[2 * p + 1], q1[2 * p + 1], d1);
        }
        // early refill (overlaps shfl chain + phase B + next dot)
        if (rn + 2 < count) LOADB(0, pcur + 2 * HDIM);
        if (rn + 3 < count) LOADB(1, pcur + 3 * HDIM);
        int gi0 = bptr[rn], gi1 = bptr[rn + 1];

        a0 = add2(a0, a1); b0 = add2(b0, b1);
        c0 = add2(c0, c1); d0 = add2(d0, d1);
        float s0 = lo2(a0) + hi2(a0);
        float s1 = lo2(b0) + hi2(b0);
        float s2 = lo2(c0) + hi2(c0);
        float s3 = lo2(d0) + hi2(d0);
#pragma unroll
        for (int o = 16; o; o >>= 1) {     // 4 interleaved butterflies
            s0 += __shfl_xor_sync(~0u, s0, o);
            s1 += __shfl_xor_sync(~0u, s1, o);
            s2 += __shfl_xor_sync(~0u, s2, o);
            s3 += __shfl_xor_sync(~0u, s3, o);
        }
        float w0 = __expf(s0), w1 = __expf(s1);
        float w2 = __expf(s2), w3 = __expf(s3);

        // node rn
        if (gi0 != cur_g) {
            if (cur_g >= 0) FLUSH();
            cur_g = gi0;
        }
        dp = add2(dp, pack2(w0, w1));
        PHASEB(pcur, dup2(w0), dup2(w1));

        // node rn+1
        if (gi1 != cur_g) {
            FLUSH();                        // cur_g >= 0 guaranteed here
            cur_g = gi1;
        }
        dp = add2(dp, pack2(w2, w3));
        PHASEB(pcur + HDIM, dup2(w2), dup2(w3));

        pcur += 2 * HDIM; rn += 2;
    }

    if (rn < count) {                       // tail single node (B0 holds it)
        U64 a0 = 0ull, a1 = 0ull, b0 = 0ull, b1 = 0ull;
#pragma unroll
        for (int p = 0; p < 4; p++) {
            a0 = fma2(B0[2 * p],     q0[2 * p],     a0);
            a1 = fma2(B0[2 * p + 1], q0[2 * p + 1], a1);
            b0 = fma2(B0[2 * p],     q1[2 * p],     b0);
            b1 = fma2(B0[2 * p + 1], q1[2 * p + 1], b1);
        }
        int gi = bptr[rn];
        a0 = add2(a0, a1); b0 = add2(b0, b1);
        float s0 = lo2(a0) + hi2(a0);
        float s1 = lo2(b0) + hi2(b0);
#pragma unroll
        for (int o = 16; o; o >>= 1) {
            s0 += __shfl_xor_sync(~0u, s0, o);
            s1 += __shfl_xor_sync(~0u, s1, o);
        }
        float w0 = __expf(s0), w1 = __expf(s1);
        if (gi != cur_g) {
            if (cur_g >= 0) FLUSH();
            cur_g = gi;
        }
        dp = add2(dp, pack2(w0, w1));
        PHASEB(pcur, dup2(w0), dup2(w1));
    }

    if (cur_g >= 0) FLUSH();
#undef PHASEB
#undef LOADB
#undef FLUSH
}

// ---------------- v-projection: grid (64 graph-blocks of 4, 8 heads) ----------------
__global__ __launch_bounds__(256) void vproj_kernel(const float* __restrict__ vw,
                                                    const float* __restrict__ vb) {
    __shared__ float Yn[4][HDIM];
    __shared__ float wt[2][64][68];
    __shared__ float invs[4], nzf[4];
    const int gb = blockIdx.x, h = blockIdx.y, t = threadIdx.x;

    if (t < 4) {
        float d = g_denom[gb * 4 + t][h];
        invs[t] = d > 0.f ? 1.f / d : 0.f;
        nzf[t]  = d > 0.f ? 1.f : 0.f;
    }
    __syncthreads();

    for (int k = t * 4; k < 4 * HDIM; k += 1024) {
        int r = k >> 9, cidx = k & 511;
        float4 v = *(const float4*)&g_y[gb * 4 + r][h][cidx];
        float s = invs[r];
        v.x *= s; v.y *= s; v.z *= s; v.w *= s;
        *(float4*)&Yn[r][cidx] = v;
    }

#define LOAD_W(KC, BUF) do {                                                  \
        _Pragma("unroll")                                                     \
        for (int k = 0; k < 4; k++) {                                         \
            int idx = t + k * 256;                                            \
            int r = idx >> 4, cc = idx & 15;                                  \
            cpa16(&wt[BUF][r][cc * 4],                                        \
                  &vw[(size_t)(h * 64 + r) * HDIM + (KC) + cc * 4]);          \
        }                                                                     \
    } while (0)

    LOAD_W(0, 0);
    CP_COMMIT();

    const int c = t & 63, gq = t >> 6;
    U64 a0 = 0ull, a1 = 0ull;

    for (int ch = 0; ch < 8; ch++) {
        CP_WAIT0();
        __syncthreads();
        if (ch + 1 < 8) LOAD_W((ch + 1) * 64, (ch + 1) & 1);
        CP_COMMIT();

        const float* wr = &wt[ch & 1][c][0];
#pragma unroll
        for (int j = 0; j < 64; j += 4) {
            ulonglong2 w2 = *(const ulonglong2*)&wr[j];
            ulonglong2 ya = *(const ulonglong2*)&Yn[gq][ch * 64 + j];
            a0 = fma2(w2.x, ya.x, a0);
            a1 = fma2(w2.y, ya.y, a1);
        }
        __syncthreads();
    }
#undef LOAD_W

    float b = vb[h * 64 + c];
    float r = lo2(a0) + hi2(a0) + lo2(a1) + hi2(a1);
    g_att[gb * 4 + gq][h * 64 + c] = r + nzf[gq] * b;
}

// ---------------- fused output projection + layer norm ----------------
// grid 64 CTAs x 4 graphs. Streams ow as 64x64 double-buffered cp.async tiles
// (flattened it = cb*8 + kc), then LNs the smem-resident rows and writes out.
__global__ __launch_bounds__(256) void oproj_ln_kernel(const float* __restrict__ ow,
                                                       const float* __restrict__ ob,
                                                       const float* __restrict__ gam,
                                                       const float* __restrict__ bet,
                                                       float* __restrict__ out) {
    extern __shared__ float sm[];
    float* As    = sm;                  // [4][512]
    float* wtb   = sm + 2048;           // [2][64][68] = 8704
    float* ores  = wtb + 8704;          // [4][512]
    float* red1  = ores + 2048;         // [8]
    float* red2  = red1 + 8;            // [8]
    float* stats = red2 + 8;            // [2]

    const int gb = blockIdx.x, t = threadIdx.x;

    for (int k = t * 4; k < 4 * HDIM; k += 1024)
        *(float4*)&As[(k >> 9) * HDIM + (k & 511)] =
            *(const float4*)&g_att[gb * 4 + (k >> 9)][k & 511];

#define LOADT(IT, BUF) do {                                                   \
        int cb_ = (IT) >> 3, kc_ = (IT) & 7;                                  \
        _Pragma("unroll")                                                     \
        for (int k = 0; k < 4; k++) {                                         \
            int idx = t + k * 256;                                            \
            int r = idx >> 4, cc = idx & 15;                                  \
            cpa16(wtb + (BUF) * 4352 + r * 68 + cc * 4,                       \
                  &ow[(size_t)(cb_ * 64 + r) * HDIM + kc_ * 64 + cc * 4]);    \
        }                                                                     \
    } while (0)

    LOADT(0, 0);
    CP_COMMIT();

    const int c = t & 63, gq = t >> 6;
    U64 a0 = 0ull, a1 = 0ull;

    for (int it = 0; it < 64; it++) {
        CP_WAIT0();
        __syncthreads();
        if (it + 1 < 64) LOADT(it + 1, (it + 1) & 1);
        CP_COMMIT();

        const int kc = it & 7;
        const float* wr = wtb + (it & 1) * 4352 + c * 68;
        const float* ar = As + gq * HDIM + kc * 64;
#pragma unroll
        for (int j = 0; j < 64; j += 4) {
            ulonglong2 w2 = *(const ulonglong2*)&wr[j];
            ulonglong2 ya = *(const ulonglong2*)&ar[j];
            a0 = fma2(w2.x, ya.x, a0);
            a1 = fma2(w2.y, ya.y, a1);
        }
        __syncthreads();

        if (kc == 7) {
            int cb = it >> 3;
            ores[gq * HDIM + cb * 64 + c] =
                lo2(a0) + hi2(a0) + lo2(a1) + hi2(a1) + ob[cb * 64 + c];
            a0 = 0ull; a1 = 0ull;
        }
    }
#undef LOADT

    __syncthreads();

    // layer norm on the 4 smem-resident rows
    for (int g = 0; g < 4; g++) {
        float v0 = ores[g * HDIM + t];
        float v1 = ores[g * HDIM + t + 256];
        float s1 = v0 + v1, s2 = v0 * v0 + v1 * v1;
#pragma unroll
        for (int o = 16; o; o >>= 1) {
            s1 += __shfl_xor_sync(~0u, s1, o);
            s2 += __shfl_xor_sync(~0u, s2, o);
        }
        if ((t & 31) == 0) { red1[t >> 5] = s1; red2[t >> 5] = s2; }
        __syncthreads();
        if (t == 0) {
            float a = 0.f, b = 0.f;
            for (int k = 0; k < 8; k++) { a += red1[k]; b += red2[k]; }
            float mu = a * (1.f / 512.f);
            stats[0] = mu;
            stats[1] = rsqrtf(b * (1.f / 512.f) - mu * mu + 1e-5f);
        }
        __syncthreads();
        float mu = stats[0], rs = stats[1];
        size_t row = (size_t)(gb * 4 + g) * HDIM;
        out[row + t]       = (v0 - mu) * rs * gam[t] + bet[t];
        out[row + t + 256] = (v1 - mu) * rs * gam[t + 256] + bet[t + 256];
        __syncthreads();
    }
}

// ---------------- launch ----------------
extern "C" void kernel_launch(void* const* d_in, const int* in_sizes, int n_in,
                              void* d_out, int out_size) {
    const float* x     = (const float*)d_in[0];
    const int*   batch = (const int*)d_in[1];
    const float* q     = (const float*)d_in[2];
    const float* kw    = (const float*)d_in[3];
    // d_in[4] = k_b: cancels in segment softmax (per-head constant shift) — unused
    const float* vw    = (const float*)d_in[5];
    const float* vb    = (const float*)d_in[6];
    const float* ow    = (const float*)d_in[7];
    const float* ob    = (const float*)d_in[8];
    const float* lng   = (const float*)d_in[9];
    const float* lnb   = (const float*)d_in[10];
    float* out = (float*)d_out;

    int N = in_sizes[0] / HDIM;

    zero_y_kernel<<<1024, 256>>>();                 // launch 1
    zero_d_kernel<<<8, 256>>>();                    // launch 2
    qk_kernel<<<64, 256>>>(q, kw);                  // launch 3

    // grid ~2 waves at 2 CTAs/SM (148 SMs)
    int CHv = ((N + 591) / 592 + 1) & ~1;
    if (CHv < 2) CHv = 2;
    int NT = (N + CHv - 1) / CHv;
    main_kernel<<<NT, 256>>>(x, batch, N, CHv);     // launch 4 (profiled slot)

    vproj_kernel<<<dim3(64, NUM_HEADS), 256>>>(vw, vb);

    size_t osm = (2048 + 8704 + 2048 + 18) * sizeof(float);
    cudaFuncSetAttribute(oproj_ln_kernel, cudaFuncAttributeMaxDynamicSharedMemorySize, (int)osm);
    oproj_ln_kernel<<<64, 256, osm>>>(ow, ob, lng, lnb, out);
}

// round 14
// speedup vs baseline: 1.1929x; 1.1929x over previous
#include <cuda_runtime.h>

typedef unsigned long long U64;

#define NUM_HEADS 8
#define HDIM 512
#define NGRAPH 256

// ---------------- device scratch (no allocations allowed) ----------------
__device__ float g_qk[NUM_HEADS * HDIM];
__device__ float g_y[NGRAPH][NUM_HEADS][HDIM];
__device__ float g_denom[NGRAPH][NUM_HEADS];
__device__ float g_att[NGRAPH][HDIM];

// ---------------- f32x2 helpers ----------------
__device__ __forceinline__ U64 fma2(U64 a, U64 b, U64 c) {
    U64 d;
    asm("fma.rn.f32x2 %0, %1, %2, %3;" : "=l"(d) : "l"(a), "l"(b), "l"(c));
    return d;
}
__device__ __forceinline__ U64 add2(U64 a, U64 b) {
    U64 d;
    asm("add.rn.f32x2 %0, %1, %2;" : "=l"(d) : "l"(a), "l"(b));
    return d;
}
__device__ __forceinline__ U64 dup2(float x) {
    U64 d; unsigned xi = __float_as_uint(x);
    asm("mov.b64 %0, {%1, %1};" : "=l"(d) : "r"(xi));
    return d;
}
__device__ __forceinline__ U64 pack2(float a, float b) {
    U64 d;
    asm("mov.b64 %0, {%1, %2};" : "=l"(d)
        : "r"(__float_as_uint(a)), "r"(__float_as_uint(b)));
    return d;
}
__device__ __forceinline__ float lo2(U64 v) { return __uint_as_float((unsigned)(v & 0xffffffffu)); }
__device__ __forceinline__ float hi2(U64 v) { return __uint_as_float((unsigned)(v >> 32)); }

__device__ __forceinline__ void cpa16(void* dst, const void* src) {
    unsigned d = (unsigned)__cvta_generic_to_shared(dst);
    asm volatile("cp.async.cg.shared.global [%0], [%1], 16;\n" :: "r"(d), "l"(src));
}
#define CP_COMMIT() asm volatile("cp.async.commit_group;\n" ::: "memory")
#define CP_WAIT0()  asm volatile("cp.async.wait_group 0;\n" ::: "memory")

// ---------------- zero kernels (atomic accumulators) ----------------
__global__ void zero_y_kernel() {
    int i = (blockIdx.x * 256 + threadIdx.x) * 4;   // 1024 CTAs -> 1,048,576 floats
    *(float4*)&(((float*)g_y)[i]) = make_float4(0.f, 0.f, 0.f, 0.f);
}
__global__ void zero_d_kernel() {
    int i = blockIdx.x * 256 + threadIdx.x;          // 8 CTAs -> 2048 floats
    ((float*)g_denom)[i] = 0.f;
}

// ---------------- qk fold (64 CTAs, smem-staged coalesced) ----------------
__global__ __launch_bounds__(256) void qk_kernel(const float* __restrict__ q,
                                                 const float* __restrict__ kw) {
    __shared__ float tile[64 * 65];
    __shared__ float qs[64];
    __shared__ float part[4][64];
    const int h = blockIdx.x >> 3, jb = blockIdx.x & 7;
    const int t = threadIdx.x;
    if (t < 64) qs[t] = q[h * 64 + t];
    for (int k = t; k < 1024; k += 256) {
        int r = k >> 4, cc = k & 15;
        float4 v = *(const float4*)&kw[(size_t)(h * 64 + r) * HDIM + jb * 64 + cc * 4];
        float* dst = &tile[r * 65 + cc * 4];
        dst[0] = v.x; dst[1] = v.y; dst[2] = v.z; dst[3] = v.w;
    }
    __syncthreads();
    const int c = t & 63, ds = t >> 6;
    float s = 0.f;
#pragma unroll
    for (int d = 0; d < 16; d++) s += qs[ds * 16 + d] * tile[(ds * 16 + d) * 65 + c];
    part[ds][c] = s;
    __syncthreads();
    if (t < 64)
        g_qk[h * HDIM + jb * 64 + t] =
            (part[0][t] + part[1][t] + part[2][t] + part[3][t]) * 0.125f;
}

// ---------------- main: register-resident, 2-node interleaved (PROC2) — R13 WIN, unchanged ----------------
__global__ __launch_bounds__(256, 2)
void main_kernel(const float* __restrict__ x, const int* __restrict__ batch,
                 int N, int CHv) {
    const int t = threadIdx.x;
    const int lane = t & 31;
    const int w = t >> 5;
    const int h0 = (w & 3) * 2;
    const int nl = w >> 2;

    U64 q0[8], q1[8];
#pragma unroll
    for (int p = 0; p < 4; p++) {
        int d = p * 128 + lane * 4;
        ulonglong2 a = *(const ulonglong2*)&g_qk[h0 * HDIM + d];
        ulonglong2 b = *(const ulonglong2*)&g_qk[(h0 + 1) * HDIM + d];
        q0[2 * p] = a.x; q0[2 * p + 1] = a.y;
        q1[2 * p] = b.x; q1[2 * p + 1] = b.y;
    }

    U64 Y0[8], Y1[8];
#pragma unroll
    for (int p = 0; p < 8; p++) { Y0[p] = 0ull; Y1[p] = 0ull; }
    U64 dp = 0ull;
    int cur_g = -1;

    const int half = CHv >> 1;
    const int nbeg = blockIdx.x * CHv + nl * half;
    const int nlim = min(nbeg + half, N);
    const int count = nlim - nbeg;

    const float* pcur = x + (size_t)nbeg * HDIM + lane * 4;
    const int* bptr = batch + nbeg;
    int rn = 0;

    U64 B0[8], B1[8];

#define FLUSH() do {                                                          \
        _Pragma("unroll")                                                     \
        for (int p = 0; p < 4; p++) {                                         \
            int d = p * 128 + lane * 4;                                       \
            atomicAdd(&g_y[cur_g][h0][d],         lo2(Y0[2 * p]));            \
            atomicAdd(&g_y[cur_g][h0][d + 1],     hi2(Y0[2 * p]));            \
            atomicAdd(&g_y[cur_g][h0][d + 2],     lo2(Y0[2 * p + 1]));        \
            atomicAdd(&g_y[cur_g][h0][d + 3],     hi2(Y0[2 * p + 1]));        \
            atomicAdd(&g_y[cur_g][h0 + 1][d],     lo2(Y1[2 * p]));            \
            atomicAdd(&g_y[cur_g][h0 + 1][d + 1], hi2(Y1[2 * p]));            \
            atomicAdd(&g_y[cur_g][h0 + 1][d + 2], lo2(Y1[2 * p + 1]));        \
            atomicAdd(&g_y[cur_g][h0 + 1][d + 3], hi2(Y1[2 * p + 1]));        \
            Y0[2 * p] = 0ull; Y0[2 * p + 1] = 0ull;                           \
            Y1[2 * p] = 0ull; Y1[2 * p + 1] = 0ull;                           \
        }                                                                     \
        if (lane == 0) {                                                      \
            atomicAdd(&g_denom[cur_g][h0],     lo2(dp));                      \
            atomicAdd(&g_denom[cur_g][h0 + 1], hi2(dp));                      \
        }                                                                     \
        dp = 0ull;                                                            \
    } while (0)

#define LOADB(SL, PTR) do {                                                   \
        _Pragma("unroll")                                                     \
        for (int p = 0; p < 4; p++) {                                         \
            ulonglong2 v = *(const ulonglong2*)&(PTR)[p * 128];               \
            B##SL[2 * p] = v.x; B##SL[2 * p + 1] = v.y;                       \
        }                                                                     \
    } while (0)

#define PHASEB(PTR, WD0, WD1) do {                                            \
        _Pragma("unroll")                                                     \
        for (int p = 0; p < 4; p++) {                                         \
            ulonglong2 v = *(const ulonglong2*)&(PTR)[p * 128];               \
            Y0[2 * p]     = fma2(WD0, v.x, Y0[2 * p]);                        \
            Y0[2 * p + 1] = fma2(WD0, v.y, Y0[2 * p + 1]);                    \
            Y1[2 * p]     = fma2(WD1, v.x, Y1[2 * p]);                        \
            Y1[2 * p + 1] = fma2(WD1, v.y, Y1[2 * p + 1]);                    \
        }                                                                     \
    } while (0)

    if (count > 0) LOADB(0, pcur);
    if (count > 1) LOADB(1, pcur + HDIM);

    while (rn + 1 < count) {
        U64 a0 = 0ull, a1 = 0ull, b0 = 0ull, b1 = 0ull;
        U64 c0 = 0ull, c1 = 0ull, d0 = 0ull, d1 = 0ull;
#pragma unroll
        for (int p = 0; p < 4; p++) {
            a0 = fma2(B0[2 * p],     q0[2 * p],     a0);
            a1 = fma2(B0[2 * p + 1], q0[2 * p + 1], a1);
            b0 = fma2(B0[2 * p],     q1[2 * p],     b0);
            b1 = fma2(B0[2 * p + 1], q1[2 * p + 1], b1);
            c0 = fma2(B1[2 * p],     q0[2 * p],     c0);
            c1 = fma2(B1[2 * p + 1], q0[2 * p + 1], c1);
            d0 = fma2(B1[2 * p],     q1[2 * p],     d0);
            d1 = fma2(B1[2 * p + 1], q1[2 * p + 1], d1);
        }
        if (rn + 2 < count) LOADB(0, pcur + 2 * HDIM);
        if (rn + 3 < count) LOADB(1, pcur + 3 * HDIM);
        int gi0 = bptr[rn], gi1 = bptr[rn + 1];

        a0 = add2(a0, a1); b0 = add2(b0, b1);
        c0 = add2(c0, c1); d0 = add2(d0, d1);
        float s0 = lo2(a0) + hi2(a0);
        float s1 = lo2(b0) + hi2(b0);
        float s2 = lo2(c0) + hi2(c0);
        float s3 = lo2(d0) + hi2(d0);
#pragma unroll
        for (int o = 16; o; o >>= 1) {
            s0 += __shfl_xor_sync(~0u, s0, o);
            s1 += __shfl_xor_sync(~0u, s1, o);
            s2 += __shfl_xor_sync(~0u, s2, o);
            s3 += __shfl_xor_sync(~0u, s3, o);
        }
        float w0 = __expf(s0), w1 = __expf(s1);
        float w2 = __expf(s2), w3 = __expf(s3);

        if (gi0 != cur_g) {
            if (cur_g >= 0) FLUSH();
            cur_g = gi0;
        }
        dp = add2(dp, pack2(w0, w1));
        PHASEB(pcur, dup2(w0), dup2(w1));

        if (gi1 != cur_g) {
            FLUSH();
            cur_g = gi1;
        }
        dp = add2(dp, pack2(w2, w3));
        PHASEB(pcur + HDIM, dup2(w2), dup2(w3));

        pcur += 2 * HDIM; rn += 2;
    }

    if (rn < count) {
        U64 a0 = 0ull, a1 = 0ull, b0 = 0ull, b1 = 0ull;
#pragma unroll
        for (int p = 0; p < 4; p++) {
            a0 = fma2(B0[2 * p],     q0[2 * p],     a0);
            a1 = fma2(B0[2 * p + 1], q0[2 * p + 1], a1);
            b0 = fma2(B0[2 * p],     q1[2 * p],     b0);
            b1 = fma2(B0[2 * p + 1], q1[2 * p + 1], b1);
        }
        int gi = bptr[rn];
        a0 = add2(a0, a1); b0 = add2(b0, b1);
        float s0 = lo2(a0) + hi2(a0);
        float s1 = lo2(b0) + hi2(b0);
#pragma unroll
        for (int o = 16; o; o >>= 1) {
            s0 += __shfl_xor_sync(~0u, s0, o);
            s1 += __shfl_xor_sync(~0u, s1, o);
        }
        float w0 = __expf(s0), w1 = __expf(s1);
        if (gi != cur_g) {
            if (cur_g >= 0) FLUSH();
            cur_g = gi;
        }
        dp = add2(dp, pack2(w0, w1));
        PHASEB(pcur, dup2(w0), dup2(w1));
    }

    if (cur_g >= 0) FLUSH();
#undef PHASEB
#undef LOADB
#undef FLUSH
}

// ---------------- v-projection: grid (64 graph-blocks of 4, 8 heads) — R12 proven ----------------
__global__ __launch_bounds__(256) void vproj_kernel(const float* __restrict__ vw,
                                                    const float* __restrict__ vb) {
    __shared__ float Yn[4][HDIM];
    __shared__ float wt[2][64][68];
    __shared__ float invs[4], nzf[4];
    const int gb = blockIdx.x, h = blockIdx.y, t = threadIdx.x;

    if (t < 4) {
        float d = g_denom[gb * 4 + t][h];
        invs[t] = d > 0.f ? 1.f / d : 0.f;
        nzf[t]  = d > 0.f ? 1.f : 0.f;
    }
    __syncthreads();

    for (int k = t * 4; k < 4 * HDIM; k += 1024) {
        int r = k >> 9, cidx = k & 511;
        float4 v = *(const float4*)&g_y[gb * 4 + r][h][cidx];
        float s = invs[r];
        v.x *= s; v.y *= s; v.z *= s; v.w *= s;
        *(float4*)&Yn[r][cidx] = v;
    }

#define LOAD_W(KC, BUF) do {                                                  \
        _Pragma("unroll")                                                     \
        for (int k = 0; k < 4; k++) {                                         \
            int idx = t + k * 256;                                            \
            int r = idx >> 4, cc = idx & 15;                                  \
            cpa16(&wt[BUF][r][cc * 4],                                        \
                  &vw[(size_t)(h * 64 + r) * HDIM + (KC) + cc * 4]);          \
        }                                                                     \
    } while (0)

    LOAD_W(0, 0);
    CP_COMMIT();

    const int c = t & 63, gq = t >> 6;
    U64 a0 = 0ull, a1 = 0ull;

    for (int ch = 0; ch < 8; ch++) {
        CP_WAIT0();
        __syncthreads();
        if (ch + 1 < 8) LOAD_W((ch + 1) * 64, (ch + 1) & 1);
        CP_COMMIT();

        const float* wr = &wt[ch & 1][c][0];
#pragma unroll
        for (int j = 0; j < 64; j += 4) {
            ulonglong2 w2 = *(const ulonglong2*)&wr[j];
            ulonglong2 ya = *(const ulonglong2*)&Yn[gq][ch * 64 + j];
            a0 = fma2(w2.x, ya.x, a0);
            a1 = fma2(w2.y, ya.y, a1);
        }
        __syncthreads();
    }
#undef LOAD_W

    float b = vb[h * 64 + c];
    float r = lo2(a0) + hi2(a0) + lo2(a1) + hi2(a1);
    g_att[gb * 4 + gq][h * 64 + c] = r + nzf[gq] * b;
}

// ---------------- output projection: grid (64 graph-blocks of 4, 8 col-blocks) — R12 proven ----------------
__global__ __launch_bounds__(256) void oproj_kernel(const float* __restrict__ ow,
                                                    const float* __restrict__ ob,
                                                    float* __restrict__ out) {
    __shared__ float As[4][HDIM];
    __shared__ float wt[2][64][68];
    const int gb = blockIdx.x, ib = blockIdx.y, t = threadIdx.x;

    for (int k = t * 4; k < 4 * HDIM; k += 1024) {
        int r = k >> 9, cidx = k & 511;
        *(float4*)&As[r][cidx] = *(const float4*)&g_att[gb * 4 + r][cidx];
    }

#define LOAD_W(KC, BUF) do {                                                  \
        _Pragma("unroll")                                                     \
        for (int k = 0; k < 4; k++) {                                         \
            int idx = t + k * 256;                                            \
            int r = idx >> 4, cc = idx & 15;                                  \
            cpa16(&wt[BUF][r][cc * 4],                                        \
                  &ow[(size_t)(ib * 64 + r) * HDIM + (KC) + cc * 4]);         \
        }                                                                     \
    } while (0)

    LOAD_W(0, 0);
    CP_COMMIT();

    const int c = t & 63, gq = t >> 6;
    U64 a0 = 0ull, a1 = 0ull;

    for (int ch = 0; ch < 8; ch++) {
        CP_WAIT0();
        __syncthreads();
        if (ch + 1 < 8) LOAD_W((ch + 1) * 64, (ch + 1) & 1);
        CP_COMMIT();

        const float* wr = &wt[ch & 1][c][0];
#pragma unroll
        for (int j = 0; j < 64; j += 4) {
            ulonglong2 w2 = *(const ulonglong2*)&wr[j];
            ulonglong2 ya = *(const ulonglong2*)&As[gq][ch * 64 + j];
            a0 = fma2(w2.x, ya.x, a0);
            a1 = fma2(w2.y, ya.y, a1);
        }
        __syncthreads();
    }
#undef LOAD_W

    float b = ob[ib * 64 + c];
    float r = lo2(a0) + hi2(a0) + lo2(a1) + hi2(a1);
    out[(size_t)(gb * 4 + gq) * HDIM + ib * 64 + c] = r + b;
}

// ---------------- layer norm (in place on d_out) — R12 proven ----------------
__global__ void ln_kernel(const float* __restrict__ gam, const float* __restrict__ bet,
                          float* __restrict__ out) {
    __shared__ float red1[8], red2[8], stats[2];
    int r = blockIdx.x, t = threadIdx.x;
    float v0 = out[(size_t)r * HDIM + t];
    float v1 = out[(size_t)r * HDIM + t + 256];
    float s1 = v0 + v1, s2 = v0 * v0 + v1 * v1;
#pragma unroll
    for (int o = 16; o; o >>= 1) {
        s1 += __shfl_xor_sync(~0u, s1, o);
        s2 += __shfl_xor_sync(~0u, s2, o);
    }
    if ((t & 31) == 0) { red1[t >> 5] = s1; red2[t >> 5] = s2; }
    __syncthreads();
    if (t == 0) {
        float a = 0.f, b = 0.f;
        for (int k = 0; k < 8; k++) { a += red1[k]; b += red2[k]; }
        float mu = a * (1.f / 512.f);
        stats[0] = mu;
        stats[1] = rsqrtf(b * (1.f / 512.f) - mu * mu + 1e-5f);
    }
    __syncthreads();
    float mu = stats[0], rs = stats[1];
    out[(size_t)r * HDIM + t]       = (v0 - mu) * rs * gam[t] + bet[t];
    out[(size_t)r * HDIM + t + 256] = (v1 - mu) * rs * gam[t + 256] + bet[t + 256];
}

// ---------------- launch ----------------
extern "C" void kernel_launch(void* const* d_in, const int* in_sizes, int n_in,
                              void* d_out, int out_size) {
    const float* x     = (const float*)d_in[0];
    const int*   batch = (const int*)d_in[1];
    const float* q     = (const float*)d_in[2];
    const float* kw    = (const float*)d_in[3];
    // d_in[4] = k_b: cancels in segment softmax (per-head constant shift) — unused
    const float* vw    = (const float*)d_in[5];
    const float* vb    = (const float*)d_in[6];
    const float* ow    = (const float*)d_in[7];
    const float* ob    = (const float*)d_in[8];
    const float* lng   = (const float*)d_in[9];
    const float* lnb   = (const float*)d_in[10];
    float* out = (float*)d_out;

    int N = in_sizes[0] / HDIM;

    zero_y_kernel<<<1024, 256>>>();                 // launch 1
    zero_d_kernel<<<8, 256>>>();                    // launch 2
    qk_kernel<<<64, 256>>>(q, kw);                  // launch 3

    // grid ~2 waves at 2 CTAs/SM (148 SMs)
    int CHv = ((N + 591) / 592 + 1) & ~1;
    if (CHv < 2) CHv = 2;
    int NT = (N + CHv - 1) / CHv;
    main_kernel<<<NT, 256>>>(x, batch, N, CHv);     // launch 4 (profiled slot)

    vproj_kernel<<<dim3(64, NUM_HEADS), 256>>>(vw, vb);
    oproj_kernel<<<dim3(64, NUM_HEADS), 256>>>(ow, ob, out);
    ln_kernel<<<NGRAPH, 256>>>(lng, lnb, out);
}